// round 14
// baseline (speedup 1.0000x reference)
#include <cuda_runtime.h>

#define THETA 0.5f
#define CS 128           // rows per chunk (per block)
#define NG 8             // row groups (one per 64-thread slice)
#define RG 16            // rows per thread (register buffer)
// header floats: s_c[128]+s_r[128]+s_w[128]+s_T[64]+s_Tg[8] = 456 (mult of 4 -> 16B aligned)
#define SM_HDR 456

// Scratch: per-chunk local endpoints + ready flags.
__device__ float g_L[1 << 20];
__device__ int   g_flag[16384];

__global__ void init_flags_kernel(int n) {
    int i = blockIdx.x * blockDim.x + threadIdx.x;
    if (i < n) g_flag[i] = 0;
}

__device__ __forceinline__ void fma4(float4& a, float w, const float4& v) {
    a.x = fmaf(w, v.x, a.x); a.y = fmaf(w, v.y, a.y);
    a.z = fmaf(w, v.z, a.z); a.w = fmaf(w, v.w, a.w);
}

__global__ __launch_bounds__(512, 1)
void ou_scan_kernel(const float* __restrict__ t,
                    const float* __restrict__ x0,
                    const float* __restrict__ z,
                    float* __restrict__ out,
                    int B, int S, int D, int chunks)
{
    extern __shared__ __align__(16) float sm[];
    float*  s_c  = sm;                  // [CS] per-row decay
    float*  s_r  = sm + CS;             // [CS] per-row noise scale
    float*  s_w  = sm + 2 * CS;         // [CS] endpoint weight r*exp(-th*(Tg_end-t))
    float*  s_T  = sm + 3 * CS;         // [64] predecessor chunk end-times
    float*  s_Tg = sm + 3 * CS + 64;    // [NG] group end-times
    float4* s_P  = (float4*)(sm + SM_HDR);   // [NG * 64] group partials

    const int b  = blockIdx.x / chunks;
    const int k  = blockIdx.x % chunks;
    const int s0 = k * CS;
    const int rows = min(CS, S - s0);
    const bool full = (rows == CS);
    const int tid = threadIdx.x;
    const int g  = tid >> 6;            // group 0..7 (owns rows g*RG .. g*RG+15)
    const int l  = tid & 63;            // float4 lane (d = 4*l)

    const float* tb = t + (size_t)b * S;
    const float Tprev = (k == 0) ? 0.0f : tb[s0 - 1];

    // ---- phase 0: per-row constants ----
    for (int i = tid; i < rows; i += 512) {
        float tc = tb[s0 + i];
        float tp = (s0 + i == 0) ? 0.0f : tb[s0 + i - 1];
        float c  = __expf(-THETA * (tc - tp));
        float r  = sqrtf(fmaxf(1.0f - c * c, 0.0f));
        s_c[i] = c;
        s_r[i] = r;
        const int gi = i / RG;
        float Tge = tb[min(s0 + (gi + 1) * RG - 1, S - 1)];
        s_w[i] = r * __expf(-THETA * (Tge - tc));
    }
    if (tid < NG) s_Tg[tid] = tb[min(s0 + (tid + 1) * RG - 1, S - 1)];
    __syncthreads();

    // ---- phase 1: load ALL own rows into registers, weighted-sum endpoint ----
    const int r0 = g * RG;
    const float4* zb4 = (const float4*)(z + ((size_t)b * S + s0 + r0) * D) + l;
    const int strd = D >> 2;            // float4 per row

    float4 zv[RG];
    float4 acc0 = make_float4(0.f, 0.f, 0.f, 0.f);
    float4 acc1 = make_float4(0.f, 0.f, 0.f, 0.f);
    if (full) {
        #pragma unroll
        for (int s = 0; s < RG; ++s) zv[s] = __ldcs(zb4 + (size_t)s * strd);
        #pragma unroll
        for (int s = 0; s < RG; ++s) {
            const float w = s_w[r0 + s];
            if (s & 1) fma4(acc1, w, zv[s]); else fma4(acc0, w, zv[s]);
        }
    } else {
        const int gr = max(0, min(RG, rows - r0));
        #pragma unroll
        for (int s = 0; s < RG; ++s)
            zv[s] = (s < gr) ? __ldcs(zb4 + (size_t)s * strd)
                             : make_float4(0.f, 0.f, 0.f, 0.f);
        for (int s = 0; s < gr; ++s) fma4(acc0, s_w[r0 + s], zv[s]);
    }
    acc0.x += acc1.x; acc0.y += acc1.y; acc0.z += acc1.z; acc0.w += acc1.w;

    float4 x0v = make_float4(0.f, 0.f, 0.f, 0.f);
    if (k == 0) {
        x0v = ((const float4*)(x0 + (size_t)b * D))[l];
        if (g == 0)   // x0 (state at time 0) folded into group-0 partial
            fma4(acc0, __expf(-THETA * s_Tg[0]), x0v);
    }
    s_P[g * 64 + l] = acc0;
    __syncthreads();

    // ---- block local endpoint + publish + release flag ----
    const int base = b * chunks;
    const int cid  = base + k;
    if (g == 0) {
        const float Tend = s_Tg[NG - 1];
        float4 Lb = make_float4(0.f, 0.f, 0.f, 0.f);
        #pragma unroll
        for (int gp = 0; gp < NG; ++gp)
            fma4(Lb, __expf(-THETA * (Tend - s_Tg[gp])), s_P[gp * 64 + l]);
        ((float4*)g_L)[(size_t)cid * 64 + l] = Lb;
    }
    __syncthreads();
    if (tid == 0) {
        asm volatile("st.release.gpu.global.b32 [%0], %1;"
                     :: "l"(&g_flag[cid]), "r"(1) : "memory");
    }

    // ---- phase 2a: PARALLEL wait on predecessor flags + gather end-times ----
    if (tid < k) {
        int f;
        do {
            asm volatile("ld.acquire.gpu.global.b32 %0, [%1];"
                         : "=r"(f) : "l"(&g_flag[base + tid]) : "memory");
            if (!f) __nanosleep(32);
        } while (!f);
        s_T[tid] = tb[(tid + 1) * CS - 1];
    }
    __syncthreads();

    // ---- phase 2b: block carry (closed form over predecessor chunks) ----
    float4 a0 = make_float4(0.f, 0.f, 0.f, 0.f);
    float4 a1 = make_float4(0.f, 0.f, 0.f, 0.f);
    const float4* Lp = ((const float4*)g_L) + (size_t)base * 64 + l;
    int j = 0;
    for (; j + 2 <= k; j += 2) {
        fma4(a0, __expf(-THETA * (Tprev - s_T[j])),     Lp[(size_t)j * 64]);
        fma4(a1, __expf(-THETA * (Tprev - s_T[j + 1])), Lp[(size_t)(j + 1) * 64]);
    }
    if (j < k)
        fma4(a0, __expf(-THETA * (Tprev - s_T[j])), Lp[(size_t)j * 64]);
    float4 carry = make_float4(a0.x + a1.x, a0.y + a1.y, a0.z + a1.z, a0.w + a1.w);

    // ---- state entering THIS thread's group ----
    const float Tgprev = (g == 0) ? Tprev : s_Tg[g - 1];
    float4 y = make_float4(0.f, 0.f, 0.f, 0.f);
    fma4(y, __expf(-THETA * (Tgprev - Tprev)), carry);
    for (int gp = 0; gp < g; ++gp)
        fma4(y, __expf(-THETA * (Tgprev - s_Tg[gp])), s_P[gp * 64 + l]);
    if (k == 0 && g == 0) {
        y.x += x0v.x; y.y += x0v.y; y.z += x0v.z; y.w += x0v.w;
    }

    // ---- phase 3: forward recurrence straight from registers, stream out ----
    float4* ob4 = (float4*)(out + ((size_t)b * S + s0 + r0) * D) + l;
    if (full) {
        #pragma unroll
        for (int s = 0; s < RG; ++s) {
            const float c = s_c[r0 + s];
            const float r = s_r[r0 + s];
            y.x = fmaf(c, y.x, r * zv[s].x);
            y.y = fmaf(c, y.y, r * zv[s].y);
            y.z = fmaf(c, y.z, r * zv[s].z);
            y.w = fmaf(c, y.w, r * zv[s].w);
            __stcs(ob4 + (size_t)s * strd, y);
        }
    } else {
        const int gr = max(0, min(RG, rows - r0));
        for (int s = 0; s < gr; ++s) {
            const float c = s_c[r0 + s];
            const float r = s_r[r0 + s];
            y.x = fmaf(c, y.x, r * zv[s].x);
            y.y = fmaf(c, y.y, r * zv[s].y);
            y.z = fmaf(c, y.z, r * zv[s].z);
            y.w = fmaf(c, y.w, r * zv[s].w);
            __stcs(ob4 + (size_t)s * strd, y);
        }
    }
}

extern "C" void kernel_launch(void* const* d_in, const int* in_sizes, int n_in,
                              void* d_out, int out_size)
{
    const float* t  = (const float*)d_in[0];   // [B,S,1]
    const float* x0 = (const float*)d_in[1];   // [B,1,D]
    const float* z  = (const float*)d_in[2];   // [B,S,D]
    float* out = (float*)d_out;                // [B,S,D]

    const long n_t  = in_sizes[0];
    const long n_x0 = in_sizes[1];
    const long n_z  = in_sizes[2];
    const int D = (int)(n_z / n_t);
    const int B = (int)(n_x0 / D);
    const int S = (int)(n_t / B);
    const int chunks = (S + CS - 1) / CS;

    const int nflags = B * chunks;
    init_flags_kernel<<<(nflags + 255) / 256, 256>>>(nflags);

    const size_t smem = SM_HDR * sizeof(float) + (size_t)(NG * 64) * sizeof(float4);
    cudaFuncSetAttribute(ou_scan_kernel,
                         cudaFuncAttributeMaxDynamicSharedMemorySize, (int)smem);
    ou_scan_kernel<<<B * chunks, 512, smem>>>(t, x0, z, out, B, S, D, chunks);
}

// round 15
// speedup vs baseline: 1.3320x; 1.3320x over previous
#include <cuda_runtime.h>

#define THETA 0.5f
#define CS 256           // rows per chunk (per block)
#define NG 4             // row subgroups per block
#define RG (CS / NG)     // rows per subgroup (64)
#define PF 4             // prefetch depth in float4 rows
// header floats: s_c[CS] + s_r[CS] + s_T[64] + s_Tg[NG] = 2*CS+64+NG = 580 -> pad to 584
#define SM_HDR 584

// Scratch: per-chunk local endpoints + ready flags.
__device__ float g_L[1 << 21];   // B*chunks*D floats max
__device__ int   g_flag[16384];

__global__ void init_flags_kernel(int n) {
    int i = blockIdx.x * blockDim.x + threadIdx.x;
    if (i < n) g_flag[i] = 0;
}

__global__ __launch_bounds__(256, 3)
void ou_scan_kernel(const float* __restrict__ t,
                    const float* __restrict__ x0,
                    const float* __restrict__ z,
                    float* __restrict__ out,
                    int B, int S, int D, int chunks)
{
    extern __shared__ __align__(16) float sm[];
    float*  s_c  = sm;                  // [CS]  per-row decay
    float*  s_r  = sm + CS;             // [CS]  per-row noise scale
    float*  s_T  = sm + 2 * CS;         // [64]  predecessor chunk end-times
    float*  s_Tg = sm + 2 * CS + 64;    // [NG]  subgroup end-times
    float4* s_Lg = (float4*)(sm + SM_HDR);   // [NG * 64] subgroup endpoints

    const int b  = blockIdx.x / chunks;
    const int k  = blockIdx.x % chunks;
    const int s0 = k * CS;
    const int rows = min(CS, S - s0);
    const bool full = (rows == CS);
    const int tid = threadIdx.x;
    const int g  = tid >> 6;            // subgroup 0..3
    const int l  = tid & 63;            // float4 lane (d = 4*l)

    const float* tb = t + (size_t)b * S;
    const float Tprev = (k == 0) ? 0.0f : tb[s0 - 1];

    // ---- phase 0: per-row constants ----
    for (int i = tid; i < rows; i += 256) {
        float tc = tb[s0 + i];
        float tp = (s0 + i == 0) ? 0.0f : tb[s0 + i - 1];
        float c  = __expf(-THETA * (tc - tp));
        s_c[i] = c;
        s_r[i] = sqrtf(fmaxf(1.0f - c * c, 0.0f));
    }
    if (tid < NG) s_Tg[tid] = tb[min(s0 + (tid + 1) * RG - 1, S - 1)];
    __syncthreads();

    // ---- phase 1: subgroup-local endpoint only (__ldcg -> L2-resident) ----
    const int r0 = g * RG;
    const float4* zb4 = (const float4*)(z + ((size_t)b * S + s0 + r0) * D) + l;
    const int strd = D >> 2;            // float4 per row

    float4 x = make_float4(0.f, 0.f, 0.f, 0.f);
    if (k == 0 && g == 0) x = ((const float4*)(x0 + (size_t)b * D))[l];

    if (full) {
        float4 cur[PF], nxt[PF];
        #pragma unroll
        for (int u = 0; u < PF; ++u) cur[u] = __ldcg(zb4 + (size_t)u * strd);
        for (int s = 0; s < RG; s += PF) {
            if (s + 2 * PF <= RG) {
                #pragma unroll
                for (int u = 0; u < PF; ++u)
                    nxt[u] = __ldcg(zb4 + (size_t)(s + PF + u) * strd);
            }
            #pragma unroll
            for (int u = 0; u < PF; ++u) {
                const float c = s_c[r0 + s + u];
                const float r = s_r[r0 + s + u];
                x.x = fmaf(c, x.x, r * cur[u].x);
                x.y = fmaf(c, x.y, r * cur[u].y);
                x.z = fmaf(c, x.z, r * cur[u].z);
                x.w = fmaf(c, x.w, r * cur[u].w);
            }
            #pragma unroll
            for (int u = 0; u < PF; ++u) cur[u] = nxt[u];
        }
    } else {
        const int gr = max(0, min(RG, rows - r0));
        for (int s = 0; s < gr; ++s) {
            const float4 zv = __ldcg(zb4 + (size_t)s * strd);
            const float c = s_c[r0 + s], r = s_r[r0 + s];
            x.x = fmaf(c, x.x, r * zv.x);
            x.y = fmaf(c, x.y, r * zv.y);
            x.z = fmaf(c, x.z, r * zv.z);
            x.w = fmaf(c, x.w, r * zv.w);
        }
    }
    s_Lg[g * 64 + l] = x;
    __syncthreads();

    // ---- publish block endpoint (combined across subgroups), release flag ----
    const int base = b * chunks;
    const int cid  = base + k;
    if (g == NG - 1) {
        const float Tend = s_Tg[NG - 1];
        float4 Lb = x;
        #pragma unroll
        for (int gp = 0; gp < NG - 1; ++gp) {
            const float w = __expf(-THETA * (Tend - s_Tg[gp]));
            const float4 Lg = s_Lg[gp * 64 + l];
            Lb.x = fmaf(w, Lg.x, Lb.x);
            Lb.y = fmaf(w, Lg.y, Lb.y);
            Lb.z = fmaf(w, Lg.z, Lb.z);
            Lb.w = fmaf(w, Lg.w, Lb.w);
        }
        ((float4*)g_L)[(size_t)cid * 64 + l] = Lb;
    }
    __syncthreads();
    if (tid == 0) {
        asm volatile("st.release.gpu.global.b32 [%0], %1;"
                     :: "l"(&g_flag[cid]), "r"(1) : "memory");
    }

    // ---- prefetch first PF rows for phase 3 (independent of the carry) ----
    float4 p3[PF];
    if (full) {
        #pragma unroll
        for (int u = 0; u < PF; ++u) p3[u] = __ldcs(zb4 + (size_t)u * strd);
    }

    // ---- phase 2a: parallel wait on predecessor flags + gather end-times ----
    if (tid < k) {
        int f;
        do {
            asm volatile("ld.acquire.gpu.global.b32 %0, [%1];"
                         : "=r"(f) : "l"(&g_flag[base + tid]) : "memory");
            if (!f) __nanosleep(32);
        } while (!f);
        s_T[tid] = tb[(tid + 1) * CS - 1];
    }
    __syncthreads();

    // ---- phase 2b: block carry (closed form over predecessor chunks) ----
    float4 a0 = make_float4(0.f, 0.f, 0.f, 0.f);
    float4 a1 = make_float4(0.f, 0.f, 0.f, 0.f);
    const float4* Lp = ((const float4*)g_L) + (size_t)base * 64 + l;
    int j = 0;
    for (; j + 2 <= k; j += 2) {
        const float w0 = __expf(-THETA * (Tprev - s_T[j]));
        const float w1 = __expf(-THETA * (Tprev - s_T[j + 1]));
        const float4 L0 = Lp[(size_t)j * 64];
        const float4 L1 = Lp[(size_t)(j + 1) * 64];
        a0.x = fmaf(w0, L0.x, a0.x); a0.y = fmaf(w0, L0.y, a0.y);
        a0.z = fmaf(w0, L0.z, a0.z); a0.w = fmaf(w0, L0.w, a0.w);
        a1.x = fmaf(w1, L1.x, a1.x); a1.y = fmaf(w1, L1.y, a1.y);
        a1.z = fmaf(w1, L1.z, a1.z); a1.w = fmaf(w1, L1.w, a1.w);
    }
    if (j < k) {
        const float w0 = __expf(-THETA * (Tprev - s_T[j]));
        const float4 L0 = Lp[(size_t)j * 64];
        a0.x = fmaf(w0, L0.x, a0.x); a0.y = fmaf(w0, L0.y, a0.y);
        a0.z = fmaf(w0, L0.z, a0.z); a0.w = fmaf(w0, L0.w, a0.w);
    }
    float4 carry = make_float4(a0.x + a1.x, a0.y + a1.y, a0.z + a1.z, a0.w + a1.w);

    // ---- state entering THIS thread's subgroup ----
    const float Tgprev = (g == 0) ? Tprev : s_Tg[g - 1];
    {
        const float wb = __expf(-THETA * (Tgprev - Tprev));   // 1.0 for g==0
        carry.x *= wb; carry.y *= wb; carry.z *= wb; carry.w *= wb;
        for (int gp = 0; gp < g; ++gp) {
            const float w = __expf(-THETA * (Tgprev - s_Tg[gp]));
            const float4 Lg = s_Lg[gp * 64 + l];
            carry.x = fmaf(w, Lg.x, carry.x);
            carry.y = fmaf(w, Lg.y, carry.y);
            carry.z = fmaf(w, Lg.z, carry.z);
            carry.w = fmaf(w, Lg.w, carry.w);
        }
    }
    if (k == 0 && g == 0) {   // seed with x0 (carry is 0 here)
        const float4 xv = ((const float4*)(x0 + (size_t)b * D))[l];
        carry.x += xv.x; carry.y += xv.y; carry.z += xv.z; carry.w += xv.w;
    }

    // ---- phase 3: re-read z (L2-resident), recompute with true carry ----
    float4* ob4 = (float4*)(out + ((size_t)b * S + s0 + r0) * D) + l;
    float4 y = carry;
    if (full) {
        float4 cur[PF], nxt[PF];
        #pragma unroll
        for (int u = 0; u < PF; ++u) cur[u] = p3[u];
        for (int s = 0; s < RG; s += PF) {
            if (s + 2 * PF <= RG) {
                #pragma unroll
                for (int u = 0; u < PF; ++u)
                    nxt[u] = __ldcs(zb4 + (size_t)(s + PF + u) * strd);
            }
            #pragma unroll
            for (int u = 0; u < PF; ++u) {
                const float c = s_c[r0 + s + u];
                const float r = s_r[r0 + s + u];
                y.x = fmaf(c, y.x, r * cur[u].x);
                y.y = fmaf(c, y.y, r * cur[u].y);
                y.z = fmaf(c, y.z, r * cur[u].z);
                y.w = fmaf(c, y.w, r * cur[u].w);
                __stcs(ob4 + (size_t)(s + u) * strd, y);
            }
            #pragma unroll
            for (int u = 0; u < PF; ++u) cur[u] = nxt[u];
        }
    } else {
        const int gr = max(0, min(RG, rows - r0));
        for (int s = 0; s < gr; ++s) {
            const float4 zv = __ldcs(zb4 + (size_t)s * strd);
            const float c = s_c[r0 + s], r = s_r[r0 + s];
            y.x = fmaf(c, y.x, r * zv.x);
            y.y = fmaf(c, y.y, r * zv.y);
            y.z = fmaf(c, y.z, r * zv.z);
            y.w = fmaf(c, y.w, r * zv.w);
            __stcs(ob4 + (size_t)s * strd, y);
        }
    }
}

extern "C" void kernel_launch(void* const* d_in, const int* in_sizes, int n_in,
                              void* d_out, int out_size)
{
    const float* t  = (const float*)d_in[0];   // [B,S,1]
    const float* x0 = (const float*)d_in[1];   // [B,1,D]
    const float* z  = (const float*)d_in[2];   // [B,S,D]
    float* out = (float*)d_out;                // [B,S,D]

    const long n_t  = in_sizes[0];
    const long n_x0 = in_sizes[1];
    const long n_z  = in_sizes[2];
    const int D = (int)(n_z / n_t);
    const int B = (int)(n_x0 / D);
    const int S = (int)(n_t / B);
    const int chunks = (S + CS - 1) / CS;

    const int nflags = B * chunks;
    init_flags_kernel<<<(nflags + 255) / 256, 256>>>(nflags);

    const size_t smem = SM_HDR * sizeof(float) + (size_t)(NG * 64) * sizeof(float4);
    cudaFuncSetAttribute(ou_scan_kernel,
                         cudaFuncAttributeMaxDynamicSharedMemorySize, (int)smem);
    ou_scan_kernel<<<B * chunks, 256, smem>>>(t, x0, z, out, B, S, D, chunks);
}

// round 16
// speedup vs baseline: 1.3439x; 1.0089x over previous
#include <cuda_runtime.h>

#define THETA 0.5f
#define CS 128           // rows per chunk
#define NG 4             // row subgroups per block
#define RG 32            // rows per subgroup
#define PF 4             // prefetch depth in float4 rows
#define SUP 8            // chunks per super-group
// header floats: s_c[128]+s_r[128]+s_T[8]+s_ST[8]+s_Tg[4] = 276 (x4=1104, 16B aligned)
#define SM_HDR 276

__device__ float g_L[1 << 20];    // per-chunk endpoints
__device__ float g_SL[1 << 17];   // per-group super endpoints
__device__ int   g_flag[8192];
__device__ int   g_sflag[2048];

__global__ void init_flags_kernel(int nf, int ns) {
    int i = blockIdx.x * blockDim.x + threadIdx.x;
    if (i < nf) g_flag[i] = 0;
    if (i < ns) g_sflag[i] = 0;
}

__device__ __forceinline__ void fma4(float4& a, float w, const float4& v) {
    a.x = fmaf(w, v.x, a.x); a.y = fmaf(w, v.y, a.y);
    a.z = fmaf(w, v.z, a.z); a.w = fmaf(w, v.w, a.w);
}

__global__ __launch_bounds__(256, 4)
void ou_scan_kernel(const float* __restrict__ t,
                    const float* __restrict__ x0,
                    const float* __restrict__ z,
                    float* __restrict__ out,
                    int B, int S, int D, int chunks, int supers)
{
    extern __shared__ __align__(16) float sm[];
    float*  s_c  = sm;                 // [CS]
    float*  s_r  = sm + CS;            // [CS]
    float*  s_T  = sm + 2 * CS;        // [SUP] sibling end-times
    float*  s_ST = sm + 2 * CS + 8;    // [SUP] super end-times
    float*  s_Tg = sm + 2 * CS + 16;   // [NG]  subgroup end-times
    float4* s_Lg = (float4*)(sm + SM_HDR);   // [NG*64] subgroup endpoints

    const int b  = blockIdx.x / chunks;
    const int k  = blockIdx.x % chunks;
    const int s0 = k * CS;
    const int rows = min(CS, S - s0);
    const bool full = (rows == CS);
    const int tid = threadIdx.x;
    const int g  = tid >> 6;
    const int l  = tid & 63;
    const int G  = k >> 3;             // super-group index
    const int kg = k & 7;              // index within group

    const float* tb = t + (size_t)b * S;
    const float Tprev = (k == 0) ? 0.0f : tb[s0 - 1];

    // ---- phase 0: per-row constants ----
    for (int i = tid; i < rows; i += 256) {
        float tc = tb[s0 + i];
        float tp = (s0 + i == 0) ? 0.0f : tb[s0 + i - 1];
        float c  = __expf(-THETA * (tc - tp));
        s_c[i] = c;
        s_r[i] = sqrtf(fmaxf(1.0f - c * c, 0.0f));
    }
    if (tid < NG) s_Tg[tid] = tb[min(s0 + (tid + 1) * RG - 1, S - 1)];
    __syncthreads();

    // ---- phase 1: subgroup-local endpoint only (default caching -> L2) ----
    const int r0 = g * RG;
    const float4* zb4 = (const float4*)(z + ((size_t)b * S + s0 + r0) * D) + l;
    const int strd = D >> 2;

    float4 x = make_float4(0.f, 0.f, 0.f, 0.f);
    if (k == 0 && g == 0) x = ((const float4*)(x0 + (size_t)b * D))[l];

    if (full) {
        float4 cur[PF], nxt[PF];
        #pragma unroll
        for (int u = 0; u < PF; ++u) cur[u] = zb4[(size_t)u * strd];
        for (int s = 0; s < RG; s += PF) {
            if (s + 2 * PF <= RG) {
                #pragma unroll
                for (int u = 0; u < PF; ++u)
                    nxt[u] = zb4[(size_t)(s + PF + u) * strd];
            }
            #pragma unroll
            for (int u = 0; u < PF; ++u) {
                const float c = s_c[r0 + s + u];
                const float r = s_r[r0 + s + u];
                x.x = fmaf(c, x.x, r * cur[u].x);
                x.y = fmaf(c, x.y, r * cur[u].y);
                x.z = fmaf(c, x.z, r * cur[u].z);
                x.w = fmaf(c, x.w, r * cur[u].w);
            }
            #pragma unroll
            for (int u = 0; u < PF; ++u) cur[u] = nxt[u];
        }
    } else {
        const int gr = max(0, min(RG, rows - r0));
        for (int s = 0; s < gr; ++s) {
            const float4 zv = zb4[(size_t)s * strd];
            const float c = s_c[r0 + s], r = s_r[r0 + s];
            x.x = fmaf(c, x.x, r * zv.x);
            x.y = fmaf(c, x.y, r * zv.y);
            x.z = fmaf(c, x.z, r * zv.z);
            x.w = fmaf(c, x.w, r * zv.w);
        }
    }
    s_Lg[g * 64 + l] = x;
    __syncthreads();

    // ---- publish LOCAL endpoint + flag ----
    const int base  = b * chunks;
    const int cid   = base + k;
    const int sbase = b * supers;
    const float Tend = s_Tg[NG - 1];
    if (g == NG - 1) {
        float4 Lb = x;
        #pragma unroll
        for (int gp = 0; gp < NG - 1; ++gp)
            fma4(Lb, __expf(-THETA * (Tend - s_Tg[gp])), s_Lg[gp * 64 + l]);
        ((float4*)g_L)[(size_t)cid * 64 + l] = Lb;
    }
    __syncthreads();
    if (tid == 0) {
        asm volatile("st.release.gpu.global.b32 [%0], %1;"
                     :: "l"(&g_flag[cid]), "r"(1) : "memory");
    }

    // ---- prefetch first PF rows for phase 3 ----
    float4 p3[PF];
    if (full) {
        #pragma unroll
        for (int u = 0; u < PF; ++u) p3[u] = __ldcs(zb4 + (size_t)u * strd);
    }

    // ---- phase 2a: parallel polls (siblings on tid<kg, supers on tid 32..32+G) ----
    if (tid < kg) {
        const int jj = (G << 3) + tid;
        int f;
        do {
            asm volatile("ld.acquire.gpu.global.b32 %0, [%1];"
                         : "=r"(f) : "l"(&g_flag[base + jj]) : "memory");
            if (!f) __nanosleep(32);
        } while (!f);
        s_T[tid] = tb[(jj + 1) * CS - 1];
    } else if (tid >= 32 && tid < 32 + G) {
        const int gi = tid - 32;
        int f;
        do {
            asm volatile("ld.acquire.gpu.global.b32 %0, [%1];"
                         : "=r"(f) : "l"(&g_sflag[sbase + gi]) : "memory");
            if (!f) __nanosleep(32);
        } while (!f);
        s_ST[gi] = tb[((gi + 1) << 3) * CS - 1];
    }
    __syncthreads();

    // ---- phase 2b: carry = sibling part + super part ----
    float4 csib = make_float4(0.f, 0.f, 0.f, 0.f);
    const float4* Lp = ((const float4*)g_L) + ((size_t)(base + (G << 3))) * 64 + l;
    for (int j = 0; j < kg; ++j)
        fma4(csib, __expf(-THETA * (Tprev - s_T[j])), Lp[(size_t)j * 64]);

    float4 carry = csib;
    const float4* SLp = ((const float4*)g_SL) + (size_t)sbase * 64 + l;
    for (int gi = 0; gi < G; ++gi)
        fma4(carry, __expf(-THETA * (Tprev - s_ST[gi])), SLp[(size_t)gi * 64]);

    // ---- super publish (last chunk of a group, not the overall last) ----
    if (kg == SUP - 1 && k != chunks - 1) {
        if (g == 0) {
            // own local endpoint Lb recomputed from subgroup partials
            float4 SL = s_Lg[(NG - 1) * 64 + l];
            #pragma unroll
            for (int gp = 0; gp < NG - 1; ++gp)
                fma4(SL, __expf(-THETA * (Tend - s_Tg[gp])), s_Lg[gp * 64 + l]);
            // + group siblings folded through the sibling carry
            fma4(SL, __expf(-THETA * (Tend - Tprev)), csib);
            ((float4*)g_SL)[(size_t)(sbase + G) * 64 + l] = SL;
        }
        __syncthreads();
        if (tid == 0) {
            asm volatile("st.release.gpu.global.b32 [%0], %1;"
                         :: "l"(&g_sflag[sbase + G]), "r"(1) : "memory");
        }
    }

    // ---- state entering THIS thread's subgroup ----
    const float Tgprev = (g == 0) ? Tprev : s_Tg[g - 1];
    {
        const float wb = __expf(-THETA * (Tgprev - Tprev));   // 1.0 for g==0
        carry.x *= wb; carry.y *= wb; carry.z *= wb; carry.w *= wb;
        for (int gp = 0; gp < g; ++gp)
            fma4(carry, __expf(-THETA * (Tgprev - s_Tg[gp])), s_Lg[gp * 64 + l]);
    }
    if (k == 0 && g == 0) {   // seed with x0 (carry is 0 here)
        const float4 xv = ((const float4*)(x0 + (size_t)b * D))[l];
        carry.x += xv.x; carry.y += xv.y; carry.z += xv.z; carry.w += xv.w;
    }

    // ---- phase 3: re-read z (L2-resident), recompute with true carry ----
    float4* ob4 = (float4*)(out + ((size_t)b * S + s0 + r0) * D) + l;
    float4 y = carry;
    if (full) {
        float4 cur[PF], nxt[PF];
        #pragma unroll
        for (int u = 0; u < PF; ++u) cur[u] = p3[u];
        for (int s = 0; s < RG; s += PF) {
            if (s + 2 * PF <= RG) {
                #pragma unroll
                for (int u = 0; u < PF; ++u)
                    nxt[u] = __ldcs(zb4 + (size_t)(s + PF + u) * strd);
            }
            #pragma unroll
            for (int u = 0; u < PF; ++u) {
                const float c = s_c[r0 + s + u];
                const float r = s_r[r0 + s + u];
                y.x = fmaf(c, y.x, r * cur[u].x);
                y.y = fmaf(c, y.y, r * cur[u].y);
                y.z = fmaf(c, y.z, r * cur[u].z);
                y.w = fmaf(c, y.w, r * cur[u].w);
                __stcs(ob4 + (size_t)(s + u) * strd, y);
            }
            #pragma unroll
            for (int u = 0; u < PF; ++u) cur[u] = nxt[u];
        }
    } else {
        const int gr = max(0, min(RG, rows - r0));
        for (int s = 0; s < gr; ++s) {
            const float4 zv = __ldcs(zb4 + (size_t)s * strd);
            const float c = s_c[r0 + s], r = s_r[r0 + s];
            y.x = fmaf(c, y.x, r * zv.x);
            y.y = fmaf(c, y.y, r * zv.y);
            y.z = fmaf(c, y.z, r * zv.z);
            y.w = fmaf(c, y.w, r * zv.w);
            __stcs(ob4 + (size_t)s * strd, y);
        }
    }
}

extern "C" void kernel_launch(void* const* d_in, const int* in_sizes, int n_in,
                              void* d_out, int out_size)
{
    const float* t  = (const float*)d_in[0];   // [B,S,1]
    const float* x0 = (const float*)d_in[1];   // [B,1,D]
    const float* z  = (const float*)d_in[2];   // [B,S,D]
    float* out = (float*)d_out;                // [B,S,D]

    const long n_t  = in_sizes[0];
    const long n_x0 = in_sizes[1];
    const long n_z  = in_sizes[2];
    const int D = (int)(n_z / n_t);
    const int B = (int)(n_x0 / D);
    const int S = (int)(n_t / B);
    const int chunks = (S + CS - 1) / CS;
    const int supers = (chunks + SUP - 1) / SUP;

    const int nflags = B * chunks;
    const int nsf    = B * supers;
    const int mx     = nflags > nsf ? nflags : nsf;
    init_flags_kernel<<<(mx + 255) / 256, 256>>>(nflags, nsf);

    const size_t smem = SM_HDR * sizeof(float) + (size_t)(NG * 64) * sizeof(float4);
    cudaFuncSetAttribute(ou_scan_kernel,
                         cudaFuncAttributeMaxDynamicSharedMemorySize, (int)smem);
    ou_scan_kernel<<<B * chunks, 256, smem>>>(t, x0, z, out, B, S, D, chunks, supers);
}

// round 17
// speedup vs baseline: 1.4522x; 1.0806x over previous
#include <cuda_runtime.h>

#define THETA 0.5f
#define CS 256           // rows per chunk (per block)
#define NG 8             // row subgroups (one per 64-thread slice)
#define RG 32            // rows per subgroup
#define PF 4             // prefetch depth in float4 rows
// header floats: s_c[256]+s_r[256]+s_T[16]+s_Tg[8] = 536 (536*4=2144, 16B aligned)
#define SM_HDR 536

// Scratch: per-chunk local endpoints + ready flags.
__device__ float g_L[1 << 20];
__device__ int   g_flag[16384];

__global__ void init_flags_kernel(int n) {
    int i = blockIdx.x * blockDim.x + threadIdx.x;
    if (i < n) g_flag[i] = 0;
}

__device__ __forceinline__ void fma4(float4& a, float w, const float4& v) {
    a.x = fmaf(w, v.x, a.x); a.y = fmaf(w, v.y, a.y);
    a.z = fmaf(w, v.z, a.z); a.w = fmaf(w, v.w, a.w);
}

__global__ __launch_bounds__(512, 2)
void ou_scan_kernel(const float* __restrict__ t,
                    const float* __restrict__ x0,
                    const float* __restrict__ z,
                    float* __restrict__ out,
                    int B, int S, int D, int chunks)
{
    extern __shared__ __align__(16) float sm[];
    float*  s_c  = sm;                  // [CS] per-row decay
    float*  s_r  = sm + CS;             // [CS] per-row noise scale
    float*  s_T  = sm + 2 * CS;         // [16] predecessor chunk end-times
    float*  s_Tg = sm + 2 * CS + 16;    // [NG] subgroup end-times
    float4* s_Lg = (float4*)(sm + SM_HDR);   // [NG * 64] subgroup endpoints

    const int b  = blockIdx.x / chunks;
    const int k  = blockIdx.x % chunks;
    const int s0 = k * CS;
    const int rows = min(CS, S - s0);
    const bool full = (rows == CS);
    const int tid = threadIdx.x;
    const int g  = tid >> 6;            // subgroup 0..7
    const int l  = tid & 63;            // float4 lane (d = 4*l)

    const float* tb = t + (size_t)b * S;
    const float Tprev = (k == 0) ? 0.0f : tb[s0 - 1];

    // ---- phase 0: per-row constants ----
    for (int i = tid; i < rows; i += 512) {
        float tc = tb[s0 + i];
        float tp = (s0 + i == 0) ? 0.0f : tb[s0 + i - 1];
        float c  = __expf(-THETA * (tc - tp));
        s_c[i] = c;
        s_r[i] = sqrtf(fmaxf(1.0f - c * c, 0.0f));
    }
    if (tid < NG) s_Tg[tid] = tb[min(s0 + (tid + 1) * RG - 1, S - 1)];
    __syncthreads();

    // ---- phase 1: subgroup-local endpoint only (default caching -> L2) ----
    const int r0 = g * RG;
    const float4* zb4 = (const float4*)(z + ((size_t)b * S + s0 + r0) * D) + l;
    const int strd = D >> 2;            // float4 per row

    float4 x = make_float4(0.f, 0.f, 0.f, 0.f);
    if (k == 0 && g == 0) x = ((const float4*)(x0 + (size_t)b * D))[l];

    if (full) {
        float4 cur[PF], nxt[PF];
        #pragma unroll
        for (int u = 0; u < PF; ++u) cur[u] = zb4[(size_t)u * strd];
        for (int s = 0; s < RG; s += PF) {
            if (s + 2 * PF <= RG) {
                #pragma unroll
                for (int u = 0; u < PF; ++u)
                    nxt[u] = zb4[(size_t)(s + PF + u) * strd];
            }
            #pragma unroll
            for (int u = 0; u < PF; ++u) {
                const float c = s_c[r0 + s + u];
                const float r = s_r[r0 + s + u];
                x.x = fmaf(c, x.x, r * cur[u].x);
                x.y = fmaf(c, x.y, r * cur[u].y);
                x.z = fmaf(c, x.z, r * cur[u].z);
                x.w = fmaf(c, x.w, r * cur[u].w);
            }
            #pragma unroll
            for (int u = 0; u < PF; ++u) cur[u] = nxt[u];
        }
    } else {
        const int gr = max(0, min(RG, rows - r0));
        for (int s = 0; s < gr; ++s) {
            const float4 zv = zb4[(size_t)s * strd];
            const float c = s_c[r0 + s], r = s_r[r0 + s];
            x.x = fmaf(c, x.x, r * zv.x);
            x.y = fmaf(c, x.y, r * zv.y);
            x.z = fmaf(c, x.z, r * zv.z);
            x.w = fmaf(c, x.w, r * zv.w);
        }
    }
    s_Lg[g * 64 + l] = x;
    __syncthreads();

    // ---- publish block endpoint (combined across subgroups), release flag ----
    const int base = b * chunks;
    const int cid  = base + k;
    const float Tend = s_Tg[NG - 1];
    if (g == NG - 1) {
        float4 Lb = x;                  // own subgroup-7 endpoint
        #pragma unroll
        for (int gp = 0; gp < NG - 1; ++gp)
            fma4(Lb, __expf(-THETA * (Tend - s_Tg[gp])), s_Lg[gp * 64 + l]);
        ((float4*)g_L)[(size_t)cid * 64 + l] = Lb;
    }
    __syncthreads();
    if (tid == 0) {
        asm volatile("st.release.gpu.global.b32 [%0], %1;"
                     :: "l"(&g_flag[cid]), "r"(1) : "memory");
    }

    // ---- prefetch first PF rows for phase 3 (independent of the carry) ----
    float4 p3[PF];
    if (full) {
        #pragma unroll
        for (int u = 0; u < PF; ++u) p3[u] = __ldcs(zb4 + (size_t)u * strd);
    }

    // ---- phase 2a: parallel wait on predecessor flags + gather end-times ----
    if (tid < k) {
        int f;
        do {
            asm volatile("ld.acquire.gpu.global.b32 %0, [%1];"
                         : "=r"(f) : "l"(&g_flag[base + tid]) : "memory");
            if (!f) __nanosleep(32);
        } while (!f);
        s_T[tid] = tb[(tid + 1) * CS - 1];
    }
    __syncthreads();

    // ---- phase 2b: block carry (closed form over predecessor chunks) ----
    float4 a0 = make_float4(0.f, 0.f, 0.f, 0.f);
    float4 a1 = make_float4(0.f, 0.f, 0.f, 0.f);
    const float4* Lp = ((const float4*)g_L) + (size_t)base * 64 + l;
    int j = 0;
    for (; j + 2 <= k; j += 2) {
        fma4(a0, __expf(-THETA * (Tprev - s_T[j])),     Lp[(size_t)j * 64]);
        fma4(a1, __expf(-THETA * (Tprev - s_T[j + 1])), Lp[(size_t)(j + 1) * 64]);
    }
    if (j < k)
        fma4(a0, __expf(-THETA * (Tprev - s_T[j])), Lp[(size_t)j * 64]);
    float4 carry = make_float4(a0.x + a1.x, a0.y + a1.y, a0.z + a1.z, a0.w + a1.w);

    // ---- state entering THIS thread's subgroup ----
    const float Tgprev = (g == 0) ? Tprev : s_Tg[g - 1];
    {
        const float wb = __expf(-THETA * (Tgprev - Tprev));   // 1.0 for g==0
        carry.x *= wb; carry.y *= wb; carry.z *= wb; carry.w *= wb;
        for (int gp = 0; gp < g; ++gp)
            fma4(carry, __expf(-THETA * (Tgprev - s_Tg[gp])), s_Lg[gp * 64 + l]);
    }
    if (k == 0 && g == 0) {   // seed with x0 (carry is 0 here)
        const float4 xv = ((const float4*)(x0 + (size_t)b * D))[l];
        carry.x += xv.x; carry.y += xv.y; carry.z += xv.z; carry.w += xv.w;
    }

    // ---- phase 3: re-read z (L2-resident), recompute with true carry ----
    float4* ob4 = (float4*)(out + ((size_t)b * S + s0 + r0) * D) + l;
    float4 y = carry;
    if (full) {
        float4 cur[PF], nxt[PF];
        #pragma unroll
        for (int u = 0; u < PF; ++u) cur[u] = p3[u];
        for (int s = 0; s < RG; s += PF) {
            if (s + 2 * PF <= RG) {
                #pragma unroll
                for (int u = 0; u < PF; ++u)
                    nxt[u] = __ldcs(zb4 + (size_t)(s + PF + u) * strd);
            }
            #pragma unroll
            for (int u = 0; u < PF; ++u) {
                const float c = s_c[r0 + s + u];
                const float r = s_r[r0 + s + u];
                y.x = fmaf(c, y.x, r * cur[u].x);
                y.y = fmaf(c, y.y, r * cur[u].y);
                y.z = fmaf(c, y.z, r * cur[u].z);
                y.w = fmaf(c, y.w, r * cur[u].w);
                __stcs(ob4 + (size_t)(s + u) * strd, y);
            }
            #pragma unroll
            for (int u = 0; u < PF; ++u) cur[u] = nxt[u];
        }
    } else {
        const int gr = max(0, min(RG, rows - r0));
        for (int s = 0; s < gr; ++s) {
            const float4 zv = __ldcs(zb4 + (size_t)s * strd);
            const float c = s_c[r0 + s], r = s_r[r0 + s];
            y.x = fmaf(c, y.x, r * zv.x);
            y.y = fmaf(c, y.y, r * zv.y);
            y.z = fmaf(c, y.z, r * zv.z);
            y.w = fmaf(c, y.w, r * zv.w);
            __stcs(ob4 + (size_t)s * strd, y);
        }
    }
}

extern "C" void kernel_launch(void* const* d_in, const int* in_sizes, int n_in,
                              void* d_out, int out_size)
{
    const float* t  = (const float*)d_in[0];   // [B,S,1]
    const float* x0 = (const float*)d_in[1];   // [B,1,D]
    const float* z  = (const float*)d_in[2];   // [B,S,D]
    float* out = (float*)d_out;                // [B,S,D]

    const long n_t  = in_sizes[0];
    const long n_x0 = in_sizes[1];
    const long n_z  = in_sizes[2];
    const int D = (int)(n_z / n_t);
    const int B = (int)(n_x0 / D);
    const int S = (int)(n_t / B);
    const int chunks = (S + CS - 1) / CS;

    const int nflags = B * chunks;
    init_flags_kernel<<<(nflags + 255) / 256, 256>>>(nflags);

    const size_t smem = SM_HDR * sizeof(float) + (size_t)(NG * 64) * sizeof(float4);
    cudaFuncSetAttribute(ou_scan_kernel,
                         cudaFuncAttributeMaxDynamicSharedMemorySize, (int)smem);
    ou_scan_kernel<<<B * chunks, 512, smem>>>(t, x0, z, out, B, S, D, chunks);
}